// round 1
// baseline (speedup 1.0000x reference)
#include <cuda_runtime.h>
#include <math.h>

#define BATCH 2
#define TLEN  1024
#define NH    8
#define HDIM  64
#define HID   512
#define KDIM  512
#define BT    (BATCH*TLEN)

// ---------------- scratch (static device allocations: allowed) ----------------
__device__ float g_xq[BT*KDIM];
__device__ float g_xk[BT*KDIM];
__device__ float g_xv[BT*KDIM];
__device__ float g_q [BT*KDIM];
__device__ float g_k [BT*KDIM];
__device__ float g_v [BT*KDIM];
__device__ float g_g [BT*KDIM];
__device__ float g_oc[BT*KDIM];
__device__ float g_act[BT*KDIM];
__device__ float g_beta [BT*NH];
__device__ float g_alpha[BT*NH];
__device__ float g_cos[TLEN*32];
__device__ float g_sin[TLEN*32];

// ---------------- GEMM: C[2048,512] = A[2048,512] @ B[512,512]^T --------------
// A row-major [M,K], B row-major [N,K] (both K-contiguous).
__device__ __forceinline__ void gemm_body(const float* __restrict__ A,
                                          const float* __restrict__ Bw,
                                          float* __restrict__ C)
{
    __shared__ __align__(16) float As[16][132];
    __shared__ __align__(16) float Bs[16][68];
    const int tid = threadIdx.x;
    const int tx = tid & 15, ty = tid >> 4;
    const int m0 = blockIdx.y * 128, n0 = blockIdx.x * 64;

    float acc[8][4];
#pragma unroll
    for (int i = 0; i < 8; i++)
#pragma unroll
        for (int j = 0; j < 4; j++) acc[i][j] = 0.0f;

    for (int kt = 0; kt < 512; kt += 16) {
#pragma unroll
        for (int i = 0; i < 2; i++) {
            int idx = tid + i * 256;
            int row = idx >> 2, kq = (idx & 3) << 2;
            float4 va = *(const float4*)(A + (size_t)(m0 + row) * 512 + kt + kq);
            As[kq + 0][row] = va.x; As[kq + 1][row] = va.y;
            As[kq + 2][row] = va.z; As[kq + 3][row] = va.w;
        }
        {
            int row = tid >> 2, kq = (tid & 3) << 2;
            float4 vb = *(const float4*)(Bw + (size_t)(n0 + row) * 512 + kt + kq);
            Bs[kq + 0][row] = vb.x; Bs[kq + 1][row] = vb.y;
            Bs[kq + 2][row] = vb.z; Bs[kq + 3][row] = vb.w;
        }
        __syncthreads();
#pragma unroll
        for (int kk = 0; kk < 16; kk++) {
            float4 a0 = *(const float4*)&As[kk][ty * 8];
            float4 a1 = *(const float4*)&As[kk][ty * 8 + 4];
            float4 b0 = *(const float4*)&Bs[kk][tx * 4];
            float av[8] = {a0.x, a0.y, a0.z, a0.w, a1.x, a1.y, a1.z, a1.w};
            float bv[4] = {b0.x, b0.y, b0.z, b0.w};
#pragma unroll
            for (int i = 0; i < 8; i++)
#pragma unroll
                for (int j = 0; j < 4; j++)
                    acc[i][j] = fmaf(av[i], bv[j], acc[i][j]);
        }
        __syncthreads();
    }
#pragma unroll
    for (int i = 0; i < 8; i++) {
        float4 o = make_float4(acc[i][0], acc[i][1], acc[i][2], acc[i][3]);
        *(float4*)(C + (size_t)(m0 + ty * 8 + i) * 512 + n0 + tx * 4) = o;
    }
}

__global__ __launch_bounds__(256) void gemm_qkvg(const float* __restrict__ x,
    const float* __restrict__ Wq, const float* __restrict__ Wk,
    const float* __restrict__ Wv, const float* __restrict__ Wg)
{
    const float* Bw; float* C;
    switch (blockIdx.z) {
        case 0:  Bw = Wq; C = g_xq; break;
        case 1:  Bw = Wk; C = g_xk; break;
        case 2:  Bw = Wv; C = g_xv; break;
        default: Bw = Wg; C = g_g;  break;
    }
    gemm_body(x, Bw, C);
}

__global__ __launch_bounds__(256) void gemm_out(const float* __restrict__ Wo,
                                                float* __restrict__ out)
{
    gemm_body(g_act, Wo, out);
}

// ---------------- beta / alpha small projection -------------------------------
__global__ __launch_bounds__(128) void small_proj(const float* __restrict__ x,
    const float* __restrict__ Wb, const float* __restrict__ bb,
    const float* __restrict__ Wgk, const float* __restrict__ bgk,
    const float* __restrict__ A_log, const float* __restrict__ dtb)
{
    __shared__ float xs[512];
    const int bt = blockIdx.x;
    const int tid = threadIdx.x;
    for (int i = tid; i < 512; i += 128) xs[i] = x[(size_t)bt * 512 + i];
    __syncthreads();
    const int warp = tid >> 5, lane = tid & 31;
#pragma unroll
    for (int oi = 0; oi < 4; oi++) {
        int out = warp * 4 + oi;
        const float* w = (out < 8) ? (Wb + out * 512) : (Wgk + (out - 8) * 512);
        float s = 0.0f;
#pragma unroll
        for (int i = 0; i < 16; i++) s = fmaf(xs[lane + i * 32], w[lane + i * 32], s);
#pragma unroll
        for (int m = 16; m; m >>= 1) s += __shfl_xor_sync(0xffffffffu, s, m);
        if (lane == 0) {
            if (out < 8) {
                float z = s + bb[out];
                g_beta[bt * 8 + out] = 1.0f / (1.0f + expf(-z));
            } else {
                int h = out - 8;
                float z = s + bgk[h] + dtb[h];
                float sp = (z > 20.0f) ? z : log1pf(expf(z));
                g_alpha[bt * 8 + h] = expf(-expf(A_log[h]) * sp);
            }
        }
    }
}

// ---------------- depthwise causal conv (width 4) + silu ----------------------
__global__ __launch_bounds__(256) void conv_silu(
    const float* __restrict__ cqw, const float* __restrict__ cqb,
    const float* __restrict__ ckw, const float* __restrict__ ckb,
    const float* __restrict__ cvw, const float* __restrict__ cvb)
{
    int idx = blockIdx.x * blockDim.x + threadIdx.x;
    if (idx >= BT * 128) return;
    const float *xin, *w, *bi; float* out;
    switch (blockIdx.y) {
        case 0:  xin = g_xq; w = cqw; bi = cqb; out = g_q; break;
        case 1:  xin = g_xk; w = ckw; bi = ckb; out = g_k; break;
        default: xin = g_xv; w = cvw; bi = cvb; out = g_v; break;
    }
    int c4 = idx & 127;
    int t  = (idx >> 7) & 1023;
    int b  = idx >> 17;
    int c  = c4 << 2;
    float4 wr0 = *(const float4*)(w + (c + 0) * 4);
    float4 wr1 = *(const float4*)(w + (c + 1) * 4);
    float4 wr2 = *(const float4*)(w + (c + 2) * 4);
    float4 wr3 = *(const float4*)(w + (c + 3) * 4);
    float wa[4] = {wr0.x, wr0.y, wr0.z, wr0.w};
    float wb2[4] = {wr1.x, wr1.y, wr1.z, wr1.w};
    float wc2[4] = {wr2.x, wr2.y, wr2.z, wr2.w};
    float wd2[4] = {wr3.x, wr3.y, wr3.z, wr3.w};
    float4 acc = *(const float4*)(bi + c);
    const float* xrow = xin + ((size_t)b * TLEN) * 512 + c;
#pragma unroll
    for (int j = 0; j < 4; j++) {
        int ti = t - 3 + j;
        if (ti >= 0) {
            float4 xv4 = *(const float4*)(xrow + (size_t)ti * 512);
            acc.x = fmaf(xv4.x, wa[j],  acc.x);
            acc.y = fmaf(xv4.y, wb2[j], acc.y);
            acc.z = fmaf(xv4.z, wc2[j], acc.z);
            acc.w = fmaf(xv4.w, wd2[j], acc.w);
        }
    }
    float4 o;
    o.x = acc.x / (1.0f + expf(-acc.x));
    o.y = acc.y / (1.0f + expf(-acc.y));
    o.z = acc.z / (1.0f + expf(-acc.z));
    o.w = acc.w / (1.0f + expf(-acc.w));
    *(float4*)(out + ((size_t)b * TLEN + t) * 512 + c) = o;
}

// ---------------- RoPE tables (fp64, recomputed every launch: deterministic) --
__global__ void rope_init()
{
    int idx = blockIdx.x * blockDim.x + threadIdx.x;
    if (idx >= TLEN * 32) return;
    int t = idx >> 5, j = idx & 31;
    const double PI = 3.14159265358979323846;
    double ar = (double)j / 32.0;
    double sbase = 10000.0 * pow(32.0, 64.0 / 62.0);
    double inv_freq = pow(sbase, -ar);
    double freq_extra = pow(10000.0, -ar);
    double wavelen = (2.0 * PI) / freq_extra;
    double ramp = (wavelen - 1.0) / 31.0;
    ramp = ramp < 0.0 ? 0.0 : (ramp > 1.0 ? 1.0 : ramp);
    double spf = 1.0 + 31.0 * ramp;
    double f = (double)t / spf * inv_freq;
    g_cos[idx] = (float)cos(f);
    g_sin[idx] = (float)sin(f);
}

// ---------------- RoPE + l2norm, in-place on g_q / g_k ------------------------
__global__ __launch_bounds__(256) void rope_l2norm()
{
    int gw = (blockIdx.x * blockDim.x + threadIdx.x) >> 5;
    int lane = threadIdx.x & 31;
    if (gw >= BT * NH) return;
    int t = (gw >> 3) & 1023;
    int j = (2 * lane) & 31;
    float c = g_cos[t * 32 + j], s = g_sin[t * 32 + j];
    size_t base = (size_t)gw * 64;
#pragma unroll
    for (int which = 0; which < 2; which++) {
        float* p = which ? g_k : g_q;
        float x1 = p[base + 2 * lane];
        float x2 = p[base + 2 * lane + 1];
        float o1 = x1 * c - x2 * s;
        float o2 = x1 * s + x2 * c;
        float ss = o1 * o1 + o2 * o2;
#pragma unroll
        for (int m = 16; m; m >>= 1) ss += __shfl_xor_sync(0xffffffffu, ss, m);
        float nrm = sqrtf(ss);
        float inv = 1.0f / fmaxf(nrm, 1e-12f);
        // shfl above synchronizes the warp: all loads complete before stores
        p[base + lane]      = o1 * inv;
        p[base + 32 + lane] = o2 * inv;
    }
}

// ---------------- delta-rule scan ---------------------------------------------
// grid (16, 4): (b*h, e-group). 256 threads: tid = el*16 + r.
// Lane owns S[d0..d0+3][e], e = eg*16+el, d0 = r*4.
__device__ __forceinline__ float red16(float x)
{
    x += __shfl_xor_sync(0xffffffffu, x, 8);
    x += __shfl_xor_sync(0xffffffffu, x, 4);
    x += __shfl_xor_sync(0xffffffffu, x, 2);
    x += __shfl_xor_sync(0xffffffffu, x, 1);
    return x;
}

__global__ __launch_bounds__(256) void scan_kernel()
{
    const int bh = blockIdx.x;           // 0..15
    const int eg = blockIdx.y;           // 0..3
    const int b = bh >> 3, h = bh & 7;
    const int tid = threadIdx.x;
    const int el = tid >> 4, r = tid & 15;
    const int e  = eg * 16 + el;
    const int d0 = r * 4;

    const size_t head = ((size_t)b * TLEN * NH + h) * 64;
    const float* qp = g_q + head;
    const float* kp = g_k + head;
    const float* vp = g_v + head;
    float*       op = g_oc + head;
    const float* ap = g_alpha + (size_t)b * TLEN * NH + h;
    const float* bp = g_beta  + (size_t)b * TLEN * NH + h;

    float4 S = make_float4(0.f, 0.f, 0.f, 0.f);

    float4 kc = *(const float4*)(kp + d0);
    float4 qc = *(const float4*)(qp + d0);
    float  vc = vp[e];
    float  ac = ap[0];
    float  bc = bp[0];

    for (int t = 0; t < TLEN; t++) {
        float4 kn = make_float4(0.f,0.f,0.f,0.f), qn = kn;
        float  vn = 0.f, an = 0.f, bn = 0.f;
        if (t + 1 < TLEN) {
            size_t off = (size_t)(t + 1) * 512;
            kn = *(const float4*)(kp + off + d0);
            qn = *(const float4*)(qp + off + d0);
            vn = vp[off + e];
            an = ap[(size_t)(t + 1) * 8];
            bn = bp[(size_t)(t + 1) * 8];
        }
        float ks = kc.x * S.x + kc.y * S.y + kc.z * S.z + kc.w * S.w;
        ks = red16(ks);
        float c1 = bc * (vc - ac * ks);
        S.x = fmaf(kc.x, c1, ac * S.x);
        S.y = fmaf(kc.y, c1, ac * S.y);
        S.z = fmaf(kc.z, c1, ac * S.z);
        S.w = fmaf(kc.w, c1, ac * S.w);
        float os = qc.x * S.x + qc.y * S.y + qc.z * S.z + qc.w * S.w;
        os = red16(os);
        if (r == 0) op[(size_t)t * 512 + e] = os;
        kc = kn; qc = qn; vc = vn; ac = an; bc = bn;
    }
}

// ---------------- post: +D*v, RMS norm, gate ----------------------------------
__global__ __launch_bounds__(256) void postproc(const float* __restrict__ D,
                                                const float* __restrict__ onw)
{
    int gw = (blockIdx.x * blockDim.x + threadIdx.x) >> 5;
    int lane = threadIdx.x & 31;
    if (gw >= BT * NH) return;
    int h = gw & 7;
    size_t base = (size_t)gw * 64;
    float d = D[h];
    float o1 = g_oc[base + lane]      + d * g_v[base + lane];
    float o2 = g_oc[base + 32 + lane] + d * g_v[base + 32 + lane];
    float ss = o1 * o1 + o2 * o2;
#pragma unroll
    for (int m = 16; m; m >>= 1) ss += __shfl_xor_sync(0xffffffffu, ss, m);
    float sc = rsqrtf(ss * (1.0f / 64.0f) + 1e-6f);
    float on1 = o1 * sc * onw[lane];
    float on2 = o2 * sc * onw[32 + lane];
    float g1 = g_g[base + lane], g2 = g_g[base + 32 + lane];
    g_act[base + lane]      = g1 * (on1 / (1.0f + expf(-on1)));
    g_act[base + 32 + lane] = g2 * (on2 / (1.0f + expf(-on2)));
}

// ---------------- launch ------------------------------------------------------
extern "C" void kernel_launch(void* const* d_in, const int* in_sizes, int n_in,
                              void* d_out, int out_size)
{
    const float* x    = (const float*)d_in[0];
    const float* Wq   = (const float*)d_in[1];
    const float* Wk   = (const float*)d_in[2];
    const float* Wv   = (const float*)d_in[3];
    const float* Wg   = (const float*)d_in[4];
    const float* Wo   = (const float*)d_in[5];
    const float* Wb   = (const float*)d_in[6];
    const float* bb   = (const float*)d_in[7];
    const float* Wgk  = (const float*)d_in[8];
    const float* bgk  = (const float*)d_in[9];
    const float* cqw  = (const float*)d_in[10];
    const float* cqb  = (const float*)d_in[11];
    const float* ckw  = (const float*)d_in[12];
    const float* ckb  = (const float*)d_in[13];
    const float* cvw  = (const float*)d_in[14];
    const float* cvb  = (const float*)d_in[15];
    const float* A_log= (const float*)d_in[16];
    const float* D    = (const float*)d_in[17];
    const float* dtb  = (const float*)d_in[18];
    const float* onw  = (const float*)d_in[19];
    float* out = (float*)d_out;

    gemm_qkvg<<<dim3(8, 16, 4), 256>>>(x, Wq, Wk, Wv, Wg);
    small_proj<<<BT, 128>>>(x, Wb, bb, Wgk, bgk, A_log, dtb);
    rope_init<<<(TLEN * 32 + 255) / 256, 256>>>();
    conv_silu<<<dim3((BT * 128 + 255) / 256, 3), 256>>>(cqw, cqb, ckw, ckb, cvw, cvb);
    rope_l2norm<<<2048, 256>>>();
    scan_kernel<<<dim3(16, 4), 256>>>();
    postproc<<<2048, 256>>>(D, onw);
    gemm_out<<<dim3(8, 16, 1), 256>>>(Wo, out);
}